// round 7
// baseline (speedup 1.0000x reference)
#include <cuda_runtime.h>

typedef unsigned long long u64;

static constexpr int TPB        = 256;
static constexpr int TILE_ROWS  = 512;               // 64 quads x 8 rows
static constexpr int TILE_BYTES = TILE_ROWS * 40;    // 20480
static constexpr int MAX_GRID   = 296;               // 2 blocks/SM

// ---- packed f32x2 helpers (ptxas only emits FFMA2 from PTX fma.rn.f32x2) ----
__device__ __forceinline__ u64 pk(float lo, float hi) {
    u64 r; asm("mov.b64 %0, {%1, %2};" : "=l"(r) : "f"(lo), "f"(hi)); return r;
}
__device__ __forceinline__ float2 upk(u64 v) {
    float2 f; asm("mov.b64 {%0, %1}, %2;" : "=f"(f.x), "=f"(f.y) : "l"(v)); return f;
}
__device__ __forceinline__ u64 fma2(u64 a, u64 b, u64 c) {
    u64 d; asm("fma.rn.f32x2 %0, %1, %2, %3;" : "=l"(d) : "l"(a), "l"(b), "l"(c)); return d;
}
__device__ __forceinline__ unsigned s2u(const void* p) {
    unsigned a;
    asm("{ .reg .u64 t; cvta.to.shared.u64 t, %1; cvt.u32.u64 %0, t; }" : "=r"(a) : "l"(p));
    return a;
}
__device__ __forceinline__ void cp16(unsigned dst, const void* src, int pred) {
    asm volatile("{ .reg .pred p; setp.ne.b32 p, %2, 0;"
                 " @p cp.async.cg.shared.global [%0], [%1], 16; }"
                 :: "r"(dst), "l"(src), "r"(pred));
}
__device__ __forceinline__ void cpcommit() {
    asm volatile("cp.async.commit_group;" ::: "memory");
}
template<int N> __device__ __forceinline__ void cpwait() {
    asm volatile("cp.async.wait_group %0;" :: "n"(N) : "memory");
}

// Quad decomposition: lanes (4q..4q+3) split the 16 hidden neurons 4-ways and
// share 8 rows; W1/b1/W2 live in REGISTERS (no weight LDS in the main loop).
// Feature-pair packing: acc_n(u64) = sum_i2 pk(x_{2i2},x_{2i2+1}) * pk(w,w'),
// h_n = acc.x + acc.y  (multiplier pairs come free from the float4 x loads).
__global__ __launch_bounds__(TPB, 2) void mlp_threshold_kernel(
    const float* __restrict__ x,
    const float* __restrict__ W1,   // [10,16] row-major
    const float* __restrict__ b1,   // [16]
    const float* __restrict__ W2,   // [16]
    const float* __restrict__ b2,   // [1]
    const float* __restrict__ thr,  // [1]
    float* __restrict__ out,        // [B] (reversed order)
    int B, int ntiles)
{
    __shared__ float4 sx[2][TILE_BYTES / 16];
    __shared__ u64 wsm[80];             // [i2*16+n] = pk(W1[2i2][n], W1[2i2+1][n])
    __shared__ float sb1[16], sw2[16];
    __shared__ float sB2, sThr;

    const int t = threadIdx.x;

    if (t < 80) {
        int i2 = t >> 4, n = t & 15;
        wsm[t] = pk(W1[(2 * i2) * 16 + n], W1[(2 * i2 + 1) * 16 + n]);
    } else if (t < 96)  sb1[t - 80] = b1[t - 80];
    else if (t < 112)   sw2[t - 96] = W2[t - 96];
    else if (t == 112) { sB2 = b2[0]; sThr = thr[0]; }

    const char* xb = (const char*)x;
    const long long total_chunks = ((long long)B / 2) * 5;   // 16B chunks of x

    auto stage = [&](int buf, int tile) {
        unsigned sdst = s2u(&sx[buf][0]);
        long long c0 = (long long)tile * (TILE_BYTES / 16);
        #pragma unroll
        for (int j = 0; j < 5; j++) {
            long long c = c0 + t + j * TPB;   // consecutive t -> consecutive 16B
            cp16(sdst + (unsigned)(t + j * TPB) * 16u, xb + c * 16, (int)(c < total_chunks));
        }
    };

    int tile = blockIdx.x;
    if (tile < ntiles) stage(0, tile);
    cpcommit();
    __syncthreads();                    // weights in smem visible

    // ---- register-resident weights for this lane's 4 neurons (4k..4k+3) ----
    const int k = t & 3;                // neuron-group within quad
    const int g = t >> 2;               // quad id 0..63
    u64 wp[5][4];
    #pragma unroll
    for (int i2 = 0; i2 < 5; i2++)
        #pragma unroll
        for (int m = 0; m < 4; m++)
            wp[i2][m] = wsm[i2 * 16 + 4 * k + m];
    u64 b1p[4];
    float w2r[4];
    #pragma unroll
    for (int m = 0; m < 4; m++) {
        b1p[m] = pk(sb1[4 * k + m], 0.0f);   // bias folded into lane .x
        w2r[m] = sw2[4 * k + m];
    }
    const float b2v = sB2, tv = sThr;

    int cur = 0;
    for (; tile < ntiles; tile += gridDim.x) {
        int nxt = tile + gridDim.x;
        bool more = (nxt < ntiles);
        if (more) stage(cur ^ 1, nxt);
        cpcommit();
        if (more) cpwait<1>(); else cpwait<0>();
        __syncthreads();

        const float4* tb = &sx[cur][0];
        float yp[8];                    // fc2 partials for quad's 8 rows

        #pragma unroll
        for (int b = 0; b < 4; b++) {
            // rows 8g+2b, 8g+2b+1 : 80B at float4 index 20g+5b (16B aligned)
            const float4* p = tb + 20 * g + 5 * b;   // all 4 lanes: same addr (broadcast)
            float4 A0 = p[0], A1 = p[1], A2 = p[2], A3 = p[3], A4 = p[4];
            u64 x0[5] = { pk(A0.x,A0.y), pk(A0.z,A0.w), pk(A1.x,A1.y), pk(A1.z,A1.w), pk(A2.x,A2.y) };
            u64 x1[5] = { pk(A2.z,A2.w), pk(A3.x,A3.y), pk(A3.z,A3.w), pk(A4.x,A4.y), pk(A4.z,A4.w) };

            u64 a0[4], a1[4];
            #pragma unroll
            for (int m = 0; m < 4; m++) {           // first step folds the bias
                a0[m] = fma2(x0[0], wp[0][m], b1p[m]);
                a1[m] = fma2(x1[0], wp[0][m], b1p[m]);
            }
            #pragma unroll
            for (int i2 = 1; i2 < 5; i2++)
                #pragma unroll
                for (int m = 0; m < 4; m++) {
                    a0[m] = fma2(x0[i2], wp[i2][m], a0[m]);
                    a1[m] = fma2(x1[i2], wp[i2][m], a1[m]);
                }

            float y0 = 0.0f, y1 = 0.0f;
            #pragma unroll
            for (int m = 0; m < 4; m++) {
                float2 h0 = upk(a0[m]);
                float2 h1 = upk(a1[m]);
                y0 = fmaf(fmaxf(h0.x + h0.y, 0.0f), w2r[m], y0);
                y1 = fmaf(fmaxf(h1.x + h1.y, 0.0f), w2r[m], y1);
            }
            yp[2 * b] = y0; yp[2 * b + 1] = y1;
        }

        // quad-reduce the 16-neuron fc2 dot (xor 1,2 stay within the quad)
        #pragma unroll
        for (int r = 0; r < 8; r++) yp[r] += __shfl_xor_sync(0xffffffffu, yp[r], 1);
        #pragma unroll
        for (int r = 0; r < 8; r++) yp[r] += __shfl_xor_sync(0xffffffffu, yp[r], 2);

        // lane k of each quad finishes+stores rows (8g+2k, 8g+2k+1)
        float yaRaw = (k == 0) ? yp[0] : (k == 1) ? yp[2] : (k == 2) ? yp[4] : yp[6];
        float ybRaw = (k == 0) ? yp[1] : (k == 1) ? yp[3] : (k == 2) ? yp[5] : yp[7];

        int r0 = tile * TILE_ROWS + 8 * g + 2 * k;
        float ya = fmaxf(yaRaw + b2v, 0.0f);
        float yb = fmaxf(ybRaw + b2v, 0.0f);
        // y >= 0 so trunc == floor; jnp.round == rint (half-to-even).
        float fa = floorf(ya); float oa = (ya - fa > tv) ? rintf(ya) : fa;
        float fb = floorf(yb); float ob = (yb - fb > tv) ? rintf(yb) : fb;

        if (r0 + 1 < B) {
            float2 o; o.x = ob; o.y = oa;   // out[B-2-r0], out[B-1-r0]
            *reinterpret_cast<float2*>(out + (B - 2 - r0)) = o;
        }
        __syncthreads();
        cur ^= 1;
    }

    // odd-B tail: last row never staged (pairs only) -> scalar from gmem
    if ((B & 1) && blockIdx.x == 0 && t == 0) {
        int r = B - 1;
        float h[16];
        #pragma unroll
        for (int n = 0; n < 16; n++) h[n] = b1[n];
        for (int i = 0; i < 10; i++) {
            float xv = x[(size_t)r * 10 + i];
            #pragma unroll
            for (int n = 0; n < 16; n++) h[n] = fmaf(xv, W1[i * 16 + n], h[n]);
        }
        float y = b2[0];
        #pragma unroll
        for (int n = 0; n < 16; n++) y = fmaf(fmaxf(h[n], 0.0f), W2[n], y);
        y = fmaxf(y, 0.0f);
        float fy = floorf(y);
        out[0] = (y - fy > thr[0]) ? rintf(y) : fy;
    }
}

extern "C" void kernel_launch(void* const* d_in, const int* in_sizes, int n_in,
                              void* d_out, int out_size) {
    const float* x   = (const float*)d_in[0];
    const float* W1  = (const float*)d_in[1];
    const float* b1  = (const float*)d_in[2];
    const float* W2  = (const float*)d_in[3];
    const float* b2  = (const float*)d_in[4];
    const float* thr = (const float*)d_in[5];
    float* out = (float*)d_out;

    int B = out_size;
    int pairs = B >> 1;
    int ntiles = (pairs + 255) / 256;               // 256 pairs (512 rows) per tile
    int grid = ntiles < MAX_GRID ? (ntiles > 0 ? ntiles : 1) : MAX_GRID;
    mlp_threshold_kernel<<<grid, TPB>>>(x, W1, b1, W2, b2, thr, out, B, ntiles);
}

// round 9
// speedup vs baseline: 1.1813x; 1.1813x over previous
#include <cuda_runtime.h>

typedef unsigned long long u64;

static constexpr int TPB        = 128;
static constexpr int TILE_PAIRS = 128;             // row-pairs per tile (= TPB)
static constexpr int TILE_BYTES = TILE_PAIRS * 80; // 10240 (pair = 2 rows * 40B)
static constexpr int MAX_GRID   = 1184;            // 8 blocks/SM persistent

// ---- packed f32x2 helpers (ptxas only emits FFMA2 from PTX fma.rn.f32x2) ----
__device__ __forceinline__ u64 pk(float lo, float hi) {
    u64 r; asm("mov.b64 %0, {%1, %2};" : "=l"(r) : "f"(lo), "f"(hi)); return r;
}
__device__ __forceinline__ float2 upk(u64 v) {
    float2 f; asm("mov.b64 {%0, %1}, %2;" : "=f"(f.x), "=f"(f.y) : "l"(v)); return f;
}
__device__ __forceinline__ u64 fma2(u64 a, u64 b, u64 c) {
    u64 d; asm("fma.rn.f32x2 %0, %1, %2, %3;" : "=l"(d) : "l"(a), "l"(b), "l"(c)); return d;
}
__device__ __forceinline__ unsigned s2u(const void* p) {
    unsigned a;
    asm("{ .reg .u64 t; cvta.to.shared.u64 t, %1; cvt.u32.u64 %0, t; }" : "=r"(a) : "l"(p));
    return a;
}
__device__ __forceinline__ void cp16(unsigned dst, const void* src, int pred) {
    asm volatile("{ .reg .pred p; setp.ne.b32 p, %2, 0;"
                 " @p cp.async.cg.shared.global [%0], [%1], 16; }"
                 :: "r"(dst), "l"(src), "r"(pred));
}
__device__ __forceinline__ void cpcommit() {
    asm volatile("cp.async.commit_group;" ::: "memory");
}
template<int N> __device__ __forceinline__ void cpwait() {
    asm volatile("cp.async.wait_group %0;" :: "n"(N) : "memory");
}

__global__ __launch_bounds__(TPB, 8) void mlp_threshold_kernel(
    const float* __restrict__ x,
    const float* __restrict__ W1,   // [10,16] row-major
    const float* __restrict__ b1,   // [16]
    const float* __restrict__ W2,   // [16]
    const float* __restrict__ b2,   // [1]
    const float* __restrict__ thr,  // [1]
    float* __restrict__ out,        // [B] (reversed order)
    int B, int pairs, int ntiles)
{
    __shared__ float4 sx[2][TILE_BYTES / 16];       // 16B-aligned x staging
    __shared__ ulonglong2 sW1[10][4];               // [i][j]: neurons 4j..4j+3 (2 packed pairs)
    __shared__ ulonglong2 sB1[4];                   // [j]: bias pairs for neurons 4j..4j+3
    __shared__ ulonglong2 sW2[4];                   // [j]: W2 pairs for neurons 4j..4j+3
    __shared__ float sB2, sThr;

    const int t = threadIdx.x;

    // ---- pack weights into smem as 16B vectors ----
    if (t < 40) {
        int i = t >> 2, j = t & 3;
        const float* w = W1 + i * 16 + 4 * j;
        ulonglong2 v;
        v.x = pk(w[0], w[1]);
        v.y = pk(w[2], w[3]);
        sW1[i][j] = v;
    } else if (t < 44) {
        int j = t - 40;
        ulonglong2 v;
        v.x = pk(b1[4 * j], b1[4 * j + 1]);
        v.y = pk(b1[4 * j + 2], b1[4 * j + 3]);
        sB1[j] = v;
    } else if (t < 48) {
        int j = t - 44;
        ulonglong2 v;
        v.x = pk(W2[4 * j], W2[4 * j + 1]);
        v.y = pk(W2[4 * j + 2], W2[4 * j + 3]);
        sW2[j] = v;
    } else if (t == 48) {
        sB2 = b2[0];
        sThr = thr[0];
    }

    const char* xb = (const char*)x;
    const long long total_chunks = (long long)pairs * 5;  // 16B chunks of x

    auto stage = [&](int buf, int tile) {
        unsigned sdst = s2u(&sx[buf][0]);
        long long c0 = (long long)tile * (TILE_PAIRS * 5);
        #pragma unroll
        for (int j = 0; j < 5; j++) {
            long long c = c0 + t + j * TPB;       // consecutive t -> consecutive 16B
            cp16(sdst + (unsigned)(t + j * TPB) * 16u, xb + c * 16, (int)(c < total_chunks));
        }
    };

    int tile = blockIdx.x;
    if (tile < ntiles) stage(0, tile);
    cpcommit();

    int cur = 0;
    for (; tile < ntiles; tile += gridDim.x) {
        int nxt = tile + gridDim.x;
        bool more = (nxt < ntiles);
        if (more) stage(cur ^ 1, nxt);
        cpcommit();
        if (more) cpwait<1>(); else cpwait<0>();
        __syncthreads();

        // ---- pair q = rows (2q, 2q+1); 80B = 5 float4, conflict-free LDS.128 ----
        int q = tile * TILE_PAIRS + t;
        bool active = (q < pairs);

        float xa[10], xbv[10];
        {
            const float4* f4 = &sx[cur][t * 5];
            float4 v0 = f4[0], v1 = f4[1], v2 = f4[2], v3 = f4[3], v4 = f4[4];
            xa[0]=v0.x; xa[1]=v0.y; xa[2]=v0.z; xa[3]=v0.w;
            xa[4]=v1.x; xa[5]=v1.y; xa[6]=v1.z; xa[7]=v1.w;
            xa[8]=v2.x; xa[9]=v2.y;
            xbv[0]=v2.z; xbv[1]=v2.w;
            xbv[2]=v3.x; xbv[3]=v3.y; xbv[4]=v3.z; xbv[5]=v3.w;
            xbv[6]=v4.x; xbv[7]=v4.y; xbv[8]=v4.z; xbv[9]=v4.w;
        }

        // acc index p = neuron pair (2p, 2p+1), p = 0..7
        u64 acc0[8], acc1[8];
        #pragma unroll
        for (int j = 0; j < 4; j++) {
            ulonglong2 bv = sB1[j];
            acc0[2*j] = bv.x; acc0[2*j+1] = bv.y;
            acc1[2*j] = bv.x; acc1[2*j+1] = bv.y;
        }

        #pragma unroll
        for (int i = 0; i < 10; i++) {
            u64 xp0 = pk(xa[i], xa[i]);
            u64 xp1 = pk(xbv[i], xbv[i]);
            #pragma unroll
            for (int j = 0; j < 4; j++) {
                ulonglong2 w = sW1[i][j];   // one broadcast LDS.128: neurons 4j..4j+3
                acc0[2*j]   = fma2(xp0, w.x, acc0[2*j]);
                acc1[2*j]   = fma2(xp1, w.x, acc1[2*j]);
                acc0[2*j+1] = fma2(xp0, w.y, acc0[2*j+1]);
                acc1[2*j+1] = fma2(xp1, w.y, acc1[2*j+1]);
            }
        }

        // relu + fc2 (packed dot with W2)
        u64 y0 = 0ull, y1 = 0ull;
        #pragma unroll
        for (int j = 0; j < 4; j++) {
            ulonglong2 wv = sW2[j];         // one broadcast LDS.128
            float2 h0, h1;
            h0 = upk(acc0[2*j]);   h1 = upk(acc1[2*j]);
            y0 = fma2(pk(fmaxf(h0.x,0.f), fmaxf(h0.y,0.f)), wv.x, y0);
            y1 = fma2(pk(fmaxf(h1.x,0.f), fmaxf(h1.y,0.f)), wv.x, y1);
            h0 = upk(acc0[2*j+1]); h1 = upk(acc1[2*j+1]);
            y0 = fma2(pk(fmaxf(h0.x,0.f), fmaxf(h0.y,0.f)), wv.y, y0);
            y1 = fma2(pk(fmaxf(h1.x,0.f), fmaxf(h1.y,0.f)), wv.y, y1);
        }
        float2 s0 = upk(y0), s1 = upk(y1);
        float bb = sB2, tt = sThr;
        float ya = fmaxf(s0.x + s0.y + bb, 0.0f);   // row 2q
        float yb = fmaxf(s1.x + s1.y + bb, 0.0f);   // row 2q+1

        // y >= 0 so trunc == floor; jnp.round == rint (half-to-even).
        float fa = floorf(ya); float oa = (ya - fa > tt) ? rintf(ya) : fa;
        float fb = floorf(yb); float ob = (yb - fb > tt) ? rintf(yb) : fb;

        if (active) {
            float2 o; o.x = ob; o.y = oa;           // out[B-2-2q], out[B-1-2q]
            *reinterpret_cast<float2*>(out + (B - 2 - 2 * q)) = o;
        }
        __syncthreads();
        cur ^= 1;
    }

    // odd-B tail (B is even in practice)
    if ((B & 1) && blockIdx.x == 0 && threadIdx.x == 0) {
        int r = B - 1;
        float h[16];
        #pragma unroll
        for (int n = 0; n < 16; n++) h[n] = b1[n];
        for (int i = 0; i < 10; i++) {
            float xv = x[(size_t)r * 10 + i];
            #pragma unroll
            for (int n = 0; n < 16; n++) h[n] = fmaf(xv, W1[i * 16 + n], h[n]);
        }
        float y = b2[0];
        #pragma unroll
        for (int n = 0; n < 16; n++) y = fmaf(fmaxf(h[n], 0.0f), W2[n], y);
        y = fmaxf(y, 0.0f);
        float fy = floorf(y);
        out[0] = (y - fy > thr[0]) ? rintf(y) : fy;
    }
}

extern "C" void kernel_launch(void* const* d_in, const int* in_sizes, int n_in,
                              void* d_out, int out_size) {
    const float* x   = (const float*)d_in[0];
    const float* W1  = (const float*)d_in[1];
    const float* b1  = (const float*)d_in[2];
    const float* W2  = (const float*)d_in[3];
    const float* b2  = (const float*)d_in[4];
    const float* thr = (const float*)d_in[5];
    float* out = (float*)d_out;

    int B = out_size;
    int pairs = B >> 1;
    int ntiles = (pairs + TILE_PAIRS - 1) / TILE_PAIRS;
    int grid = ntiles < MAX_GRID ? (ntiles > 0 ? ntiles : 1) : MAX_GRID;
    mlp_threshold_kernel<<<grid, TPB>>>(x, W1, b1, W2, b2, thr, out, B, pairs, ntiles);
}